// round 13
// baseline (speedup 1.0000x reference)
#include <cuda_runtime.h>
#include <cuda_fp16.h>

#define L1N 512
#define L2N 512
#define BB  2
#define D1N 256
#define D2N 256
#define BNN 256
#define NEGC (-1.0e12f)

typedef unsigned long long u64;

// ---------------- device scratch (no allocations allowed) ----------------
__device__ float g_p1h[2][BB*L1N*BNN];   // K-split halves of p1 [b][l][k]
__device__ float g_p2h[2][BB*L2N*BNN];   // K-split halves of p2 (+bh in half 0)
__device__ float g_q1[BB*L1N*BNN];       // [b][l][k]
__device__ float g_q2[BB*L2N*BNN];       // [b][m][k]
__device__ float g_aff [BB*L1N*L2N];     // [b][l][m]
__device__ float g_afft[BB*L2N*L1N];     // [b][m][l]
__device__ float g_d12 [BB*L1N*L2N];     // softmax over m      [b][l][m]
__device__ float g_d21t[BB*L2N*L1N];     // softmax over l, T'd [b][m][l]
__device__ float g_c12h[2][BB*L2N*D1N];  // K-split halves [b][m][d]
__device__ float g_c21h[2][BB*L1N*D2N];  // K-split halves [b][l][d]

__device__ __forceinline__ u64 pack2(float v){
    u64 r; unsigned u = __float_as_uint(v);
    asm("mov.b64 %0, {%1, %2};" : "=l"(r) : "r"(u), "r"(u)); return r;
}
__device__ __forceinline__ u64 fma2(u64 a, u64 b, u64 c){
    u64 d; asm("fma.rn.f32x2 %0, %1, %2, %3;" : "=l"(d) : "l"(a), "l"(b), "l"(c));
    return d;
}
__device__ __forceinline__ float2 unpack2(u64 v){
    unsigned lo, hi;
    asm("mov.b64 {%0, %1}, %2;" : "=r"(lo), "=r"(hi) : "l"(v));
    return make_float2(__uint_as_float(lo), __uint_as_float(hi));
}
__device__ __forceinline__ float4 f4add(float4 a, float4 b){
    return make_float4(a.x+b.x, a.y+b.y, a.z+b.z, a.w+b.w);
}
// in-place packed half2 tanh (MUFU, no conversions)
__device__ __forceinline__ __half2 tanh_h2(__half2 x){
    unsigned u = *reinterpret_cast<unsigned*>(&x);
    asm("tanh.approx.f16x2 %0, %0;" : "+r"(u));
    return *reinterpret_cast<__half2*>(&u);
}

// 8×fma2 inner step on one k-slice of a 4x4 (as 4x2-pair) tile
#define FMA2_STEP(As_, Bs_, kk_)                                            \
    {                                                                        \
        const float4 a = *(const float4*)&As_[kk_][ti];                      \
        const ulonglong2 bb = *(const ulonglong2*)&Bs_[kk_][tj];             \
        const u64 a0 = pack2(a.x), a1 = pack2(a.y),                          \
                  a2 = pack2(a.z), a3 = pack2(a.w);                          \
        acc[0][0]=fma2(a0,bb.x,acc[0][0]); acc[0][1]=fma2(a0,bb.y,acc[0][1]);\
        acc[1][0]=fma2(a1,bb.x,acc[1][0]); acc[1][1]=fma2(a1,bb.y,acc[1][1]);\
        acc[2][0]=fma2(a2,bb.x,acc[2][0]); acc[2][1]=fma2(a2,bb.y,acc[2][1]);\
        acc[3][0]=fma2(a3,bb.x,acc[3][0]); acc[3][1]=fma2(a3,bb.y,acc[3][1]);\
    }

// =====================================================================
// p-projections, K-split 2x (R11 shape: 64x64, 256 threads):
//  mode0: p1 = ctx1 @ Wh[:D1]      mode1: p2 = ctx2 @ Wh[D1:] (+bh, half 0)
// grid (4, 8, 8): x=j0, y=i0, z = mode*4 + b*2 + ks. 256 threads.
// =====================================================================
__global__ __launch_bounds__(256) void proj_p_kernel(
    const float* __restrict__ ctx1, const float* __restrict__ ctx2,
    const float* __restrict__ Wh,  const float* __restrict__ bh)
{
    const int mode = blockIdx.z >> 2;
    const int b    = (blockIdx.z >> 1) & 1;
    const int ks   = blockIdx.z & 1;
    const float* X = mode ? ctx2 : ctx1;
    const float* W = mode ? (Wh + (size_t)D1N*BNN) : Wh;
    float* P       = mode ? g_p2h[ks] : g_p1h[ks];
    const bool addb = (mode == 1) && (ks == 0);

    const int i0 = blockIdx.y * 64;
    const int j0 = blockIdx.x * 64;
    const int k00 = ks * 128;
    const int tid = threadIdx.x;
    __shared__ __align__(16) float As[2][16][68];
    __shared__ __align__(16) float Bs[2][16][64];
    u64 acc[4][2] = {};
    const int ai = tid >> 2, ad = (tid & 3) << 2;
    const int bk = tid >> 4, bj = (tid & 15) << 2;
    const int ti = (tid >> 4) << 2, tj = (tid & 15) << 2;

    const size_t arow = ((size_t)(i0+ai)*BB + b)*D1N + k00 + ad;
    float4 rA = *(const float4*)&X[arow];
    float4 rB = *(const float4*)&W[(size_t)(k00+bk)*BNN + j0 + bj];
    As[0][ad+0][ai]=rA.x; As[0][ad+1][ai]=rA.y; As[0][ad+2][ai]=rA.z; As[0][ad+3][ai]=rA.w;
    *(float4*)&Bs[0][bk][bj] = rB;
    __syncthreads();

    const int T = 128/16;
    #pragma unroll 1
    for (int t = 0; t < T; ++t) {
        const int cur = t & 1;
        if (t+1 < T) {
            rA = *(const float4*)&X[arow + (t+1)*16];
            rB = *(const float4*)&W[(size_t)(k00+(t+1)*16+bk)*BNN + j0 + bj];
        }
        #pragma unroll
        for (int k = 0; k < 16; ++k) FMA2_STEP(As[cur], Bs[cur], k);
        if (t+1 < T) {
            const int nxt = cur ^ 1;
            As[nxt][ad+0][ai]=rA.x; As[nxt][ad+1][ai]=rA.y;
            As[nxt][ad+2][ai]=rA.z; As[nxt][ad+3][ai]=rA.w;
            *(float4*)&Bs[nxt][bk][bj] = rB;
            __syncthreads();
        }
    }
    float4 bb = addb ? *(const float4*)&bh[j0+tj] : make_float4(0.f,0.f,0.f,0.f);
    #pragma unroll
    for (int r=0;r<4;r++){
        float2 lo = unpack2(acc[r][0]), hi = unpack2(acc[r][1]);
        float4 o = make_float4(lo.x+bb.x, lo.y+bb.y, hi.x+bb.z, hi.y+bb.w);
        *(float4*)&P[((size_t)(b*L1N)+(i0+ti+r))*BNN + j0 + tj] = o;
    }
}

// =====================================================================
// Heterogeneous: affinity (z=0,1) + q-projections (z=2: q1, z=3: q2).
// grid (8, 8, 4), 256 threads.  (unchanged from R11 best)
// =====================================================================
__global__ __launch_bounds__(256) void affinity_q_kernel(
    const float* __restrict__ ctx1, const float* __restrict__ ctx2,
    const float* __restrict__ m1, const float* __restrict__ m2,
    const float* __restrict__ wo,
    const float* __restrict__ W12, const float* __restrict__ W21)
{
    const int tid = threadIdx.x;
    if (blockIdx.z >= 2) {
        // ---------------- q-projection path ----------------
        const int qmode = blockIdx.z - 2;          // 0: q1, 1: q2
        const float* X = qmode ? ctx2 : ctx1;
        const float* W = qmode ? W12  : W21;
        float* P       = qmode ? g_q2 : g_q1;
        const int b  = blockIdx.x >> 2;
        const int j0 = (blockIdx.x & 3) * 64;
        const int i0 = blockIdx.y * 64;
        __shared__ __align__(16) float As[2][16][68];
        __shared__ __align__(16) float Bs[2][16][64];
        u64 acc[4][2] = {};
        const int ai = tid >> 2, ad = (tid & 3) << 2;
        const int bk = tid >> 4, bj = (tid & 15) << 2;
        const int ti = (tid >> 4) << 2, tj = (tid & 15) << 2;

        const size_t arow = ((size_t)(i0+ai)*BB + b)*D1N + ad;
        float4 rA = *(const float4*)&X[arow];
        float4 rB = *(const float4*)&W[(size_t)bk*BNN + j0 + bj];
        As[0][ad+0][ai]=rA.x; As[0][ad+1][ai]=rA.y; As[0][ad+2][ai]=rA.z; As[0][ad+3][ai]=rA.w;
        *(float4*)&Bs[0][bk][bj] = rB;
        __syncthreads();

        const int T = D1N/16;
        #pragma unroll 1
        for (int t = 0; t < T; ++t) {
            const int cur = t & 1;
            if (t+1 < T) {
                rA = *(const float4*)&X[arow + (t+1)*16];
                rB = *(const float4*)&W[(size_t)((t+1)*16+bk)*BNN + j0 + bj];
            }
            #pragma unroll
            for (int k = 0; k < 16; ++k) FMA2_STEP(As[cur], Bs[cur], k);
            if (t+1 < T) {
                const int nxt = cur ^ 1;
                As[nxt][ad+0][ai]=rA.x; As[nxt][ad+1][ai]=rA.y;
                As[nxt][ad+2][ai]=rA.z; As[nxt][ad+3][ai]=rA.w;
                *(float4*)&Bs[nxt][bk][bj] = rB;
                __syncthreads();
            }
        }
        #pragma unroll
        for (int r=0;r<4;r++){
            float2 lo = unpack2(acc[r][0]), hi = unpack2(acc[r][1]);
            *(float4*)&P[((size_t)(b*L1N)+(i0+ti+r))*BNN + j0 + tj]
                = make_float4(lo.x,lo.y,hi.x,hi.y);
        }
        return;
    }
    // ---------------- affinity path (all-fp16 inner loop) ----------------
    const int b  = blockIdx.z;
    const int l0 = blockIdx.y * 64;
    const int m0 = blockIdx.x * 64;
    __shared__ __align__(16) __half P1s[2][16][72];   // [buf][k][l-col], half
    __shared__ __align__(16) __half P2s[2][16][72];   // [buf][k][m-col], half
    __shared__ __half2 wos2[BNN];
    wos2[tid] = __float2half2_rn(wo[tid]);
    float acc[4][4] = {};
    const int ai = tid >> 2, ad = (tid & 3) << 2;
    const int ti = (tid >> 4) << 2, tm = (tid & 15) << 2;

    const size_t prow1 = ((size_t)(b*L1N)+(l0+ai))*BNN + ad;
    const size_t prow2 = ((size_t)(b*L2N)+(m0+ai))*BNN + ad;
    float4 rA = f4add(*(const float4*)&g_p1h[0][prow1],
                      *(const float4*)&g_p1h[1][prow1]);
    float4 rB = f4add(*(const float4*)&g_p2h[0][prow2],
                      *(const float4*)&g_p2h[1][prow2]);
    P1s[0][ad+0][ai]=__float2half(rA.x); P1s[0][ad+1][ai]=__float2half(rA.y);
    P1s[0][ad+2][ai]=__float2half(rA.z); P1s[0][ad+3][ai]=__float2half(rA.w);
    P2s[0][ad+0][ai]=__float2half(rB.x); P2s[0][ad+1][ai]=__float2half(rB.y);
    P2s[0][ad+2][ai]=__float2half(rB.z); P2s[0][ad+3][ai]=__float2half(rB.w);
    __syncthreads();

    const int T = BNN/16;
    #pragma unroll 1
    for (int t = 0; t < T; ++t) {
        const int cur = t & 1;
        if (t+1 < T) {
            rA = f4add(*(const float4*)&g_p1h[0][prow1 + (t+1)*16],
                       *(const float4*)&g_p1h[1][prow1 + (t+1)*16]);
            rB = f4add(*(const float4*)&g_p2h[0][prow2 + (t+1)*16],
                       *(const float4*)&g_p2h[1][prow2 + (t+1)*16]);
        }
        __half2 hacc[4][2];
        #pragma unroll
        for (int r=0;r<4;r++){ hacc[r][0]=__half2half2(__ushort_as_half(0));
                               hacc[r][1]=__half2half2(__ushort_as_half(0)); }
        #pragma unroll
        for (int kk = 0; kk < 16; ++kk) {
            const __half2 w2 = wos2[t*16+kk];
            __half a4[4];
            *reinterpret_cast<uint2*>(a4)
                = *reinterpret_cast<const uint2*>(&P1s[cur][kk][ti]);
            __half2 cv[2];
            *reinterpret_cast<uint2*>(cv)
                = *reinterpret_cast<const uint2*>(&P2s[cur][kk][tm]);
            #pragma unroll
            for (int r=0;r<4;r++){
                const __half2 ar2 = __half2half2(a4[r]);
                const __half2 t0 = tanh_h2(__hadd2(ar2, cv[0]));
                const __half2 t1 = tanh_h2(__hadd2(ar2, cv[1]));
                hacc[r][0] = __hfma2(w2, t0, hacc[r][0]);
                hacc[r][1] = __hfma2(w2, t1, hacc[r][1]);
            }
        }
        #pragma unroll
        for (int r=0;r<4;r++){
            const float2 f0 = __half22float2(hacc[r][0]);
            const float2 f1 = __half22float2(hacc[r][1]);
            acc[r][0]+=f0.x; acc[r][1]+=f0.y; acc[r][2]+=f1.x; acc[r][3]+=f1.y;
        }
        if (t+1 < T) {
            const int nxt = cur ^ 1;
            P1s[nxt][ad+0][ai]=__float2half(rA.x); P1s[nxt][ad+1][ai]=__float2half(rA.y);
            P1s[nxt][ad+2][ai]=__float2half(rA.z); P1s[nxt][ad+3][ai]=__float2half(rA.w);
            P2s[nxt][ad+0][ai]=__float2half(rB.x); P2s[nxt][ad+1][ai]=__float2half(rB.y);
            P2s[nxt][ad+2][ai]=__float2half(rB.z); P2s[nxt][ad+3][ai]=__float2half(rB.w);
            __syncthreads();
        }
    }
    float mrow[4], mcol[4];
    #pragma unroll
    for (int r=0;r<4;r++) mrow[r] = (1.0f - m1[(l0+ti+r)*BB + b]) * NEGC;
    #pragma unroll
    for (int c=0;c<4;c++) mcol[c] = (1.0f - m2[(m0+tm+c)*BB + b]) * NEGC;
    #pragma unroll
    for (int r=0;r<4;r++)
        #pragma unroll
        for (int c=0;c<4;c++)
            acc[r][c] += mrow[r] + mcol[c];
    #pragma unroll
    for (int r=0;r<4;r++)
        *(float4*)&g_aff[((size_t)(b*L1N)+(l0+ti+r))*L2N + m0 + tm]
            = make_float4(acc[r][0],acc[r][1],acc[r][2],acc[r][3]);
    #pragma unroll
    for (int c=0;c<4;c++)
        *(float4*)&g_afft[((size_t)(b*L2N)+(m0+tm+c))*L1N + l0 + ti]
            = make_float4(acc[0][c],acc[1][c],acc[2][c],acc[3][c]);
}

// =====================================================================
// Dual row softmax: grid (B*512, 2)
// =====================================================================
__global__ __launch_bounds__(128) void softmax_dual_kernel()
{
    const int row = blockIdx.x;
    const float* src = blockIdx.y ? g_afft : g_aff;
    float*       dst = blockIdx.y ? g_d21t : g_d12;
    const float4 v = ((const float4*)&src[(size_t)row*512])[threadIdx.x];
    float mx = fmaxf(fmaxf(v.x,v.y), fmaxf(v.z,v.w));
    #pragma unroll
    for (int o=16;o;o>>=1) mx = fmaxf(mx, __shfl_xor_sync(0xffffffffu, mx, o));
    __shared__ float redm[4], reds[4];
    const int wid = threadIdx.x >> 5, lane = threadIdx.x & 31;
    if (!lane) redm[wid] = mx;
    __syncthreads();
    mx = fmaxf(fmaxf(redm[0],redm[1]), fmaxf(redm[2],redm[3]));
    float e0=__expf(v.x-mx), e1=__expf(v.y-mx), e2=__expf(v.z-mx), e3=__expf(v.w-mx);
    float s = (e0+e1)+(e2+e3);
    #pragma unroll
    for (int o=16;o;o>>=1) s += __shfl_xor_sync(0xffffffffu, s, o);
    if (!lane) reds[wid] = s;
    __syncthreads();
    s = (reds[0]+reds[1])+(reds[2]+reds[3]);
    const float inv = 1.0f / s;
    ((float4*)&dst[(size_t)row*512])[threadIdx.x]
        = make_float4(e0*inv, e1*inv, e2*inv, e3*inv);
}

// =====================================================================
// Context GEMMs, K-split 2x, 64x64 tile, 128 threads, 4x8/thread:
//  which=0: c12[b,m,d] = sum_l d12 [b,l,m] * ctx1[l,b,d]
//  which=1: c21[b,l,d] = sum_m d21t[b,m,l] * ctx2[m,b,d]
// grid (4, 8, 8): x=j0(64), y=i0(64), z = which*4 + b*2 + ks. 256 blocks.
// 4x8 thread tile: 48B LDS per 32 MACs (1.5 B/MAC vs 2.0 for 4x4).
// =====================================================================
__global__ __launch_bounds__(128) void context_kernel(
    const float* __restrict__ ctx1, const float* __restrict__ ctx2)
{
    const int which = blockIdx.z >> 2;
    const int b     = (blockIdx.z >> 1) & 1;
    const int ks    = blockIdx.z & 1;
    const float* Asrc = which ? g_d21t : g_d12;
    const float* Bsrc = which ? ctx2   : ctx1;
    float*       Cdst = which ? g_c21h[ks] : g_c12h[ks];
    const int i0 = blockIdx.y * 64;
    const int j0 = blockIdx.x * 64;
    const int k00 = ks * 256;
    const int tid = threadIdx.x;
    __shared__ __align__(16) float As[2][16][64];
    __shared__ __align__(16) float Bs[2][16][64];
    u64 acc[4][4] = {};
    // staging: each thread copies 2 float4 for As and 2 float4 for Bs
    const int ak = tid >> 3, am = (tid & 7) << 3;      // ak 0..15, am 0..56 by 8
    const int bk = tid >> 3, bj = (tid & 7) << 3;
    // compute: 16 row-groups x 8 col-groups
    const int ti = (tid >> 3) << 2;                    // 0..60 by 4
    const int tj = (tid & 7) << 3;                     // 0..56 by 8
    const size_t bbase = (size_t)b * L1N;

    float4 rA0, rA1, rB0, rB1;
    rA0 = *(const float4*)&Asrc[(bbase+(k00+ak))*L2N + i0 + am];
    rA1 = *(const float4*)&Asrc[(bbase+(k00+ak))*L2N + i0 + am + 4];
    rB0 = *(const float4*)&Bsrc[((size_t)(k00+bk)*BB + b)*D1N + j0 + bj];
    rB1 = *(const float4*)&Bsrc[((size_t)(k00+bk)*BB + b)*D1N + j0 + bj + 4];
    *(float4*)&As[0][ak][am  ] = rA0;
    *(float4*)&As[0][ak][am+4] = rA1;
    *(float4*)&Bs[0][bk][bj  ] = rB0;
    *(float4*)&Bs[0][bk][bj+4] = rB1;
    __syncthreads();

    const int T = 256/16;
    #pragma unroll 1
    for (int t = 0; t < T; ++t) {
        const int cur = t & 1;
        if (t+1 < T) {
            const int kn = k00 + (t+1)*16;
            rA0 = *(const float4*)&Asrc[(bbase+(kn+ak))*L2N + i0 + am];
            rA1 = *(const float4*)&Asrc[(bbase+(kn+ak))*L2N + i0 + am + 4];
            rB0 = *(const float4*)&Bsrc[((size_t)(kn+bk)*BB + b)*D1N + j0 + bj];
            rB1 = *(const float4*)&Bsrc[((size_t)(kn+bk)*BB + b)*D1N + j0 + bj + 4];
        }
        #pragma unroll
        for (int kk = 0; kk < 16; ++kk) {
            const float4 a = *(const float4*)&As[cur][kk][ti];
            const ulonglong2 b0 = *(const ulonglong2*)&Bs[cur][kk][tj];
            const ulonglong2 b1 = *(const ulonglong2*)&Bs[cur][kk][tj+4];
            const u64 ap[4] = {pack2(a.x), pack2(a.y), pack2(a.z), pack2(a.w)};
            #pragma unroll
            for (int r=0;r<4;r++){
                acc[r][0]=fma2(ap[r],b0.x,acc[r][0]);
                acc[r][1]=fma2(ap[r],b0.y,acc[r][1]);
                acc[r][2]=fma2(ap[r],b1.x,acc[r][2]);
                acc[r][3]=fma2(ap[r],b1.y,acc[r][3]);
            }
        }
        if (t+1 < T) {
            const int nxt = cur ^ 1;
            *(float4*)&As[nxt][ak][am  ] = rA0;
            *(float4*)&As[nxt][ak][am+4] = rA1;
            *(float4*)&Bs[nxt][bk][bj  ] = rB0;
            *(float4*)&Bs[nxt][bk][bj+4] = rB1;
            __syncthreads();
        }
    }
    #pragma unroll
    for (int r=0;r<4;r++){
        float2 l0v = unpack2(acc[r][0]), l1v = unpack2(acc[r][1]);
        float2 h0v = unpack2(acc[r][2]), h1v = unpack2(acc[r][3]);
        *(float4*)&Cdst[(bbase+(i0+ti+r))*D1N + j0 + tj]
            = make_float4(l0v.x,l0v.y,l1v.x,l1v.y);
        *(float4*)&Cdst[(bbase+(i0+ti+r))*D1N + j0 + tj + 4]
            = make_float4(h0v.x,h0v.y,h1v.x,h1v.y);
    }
}

// =====================================================================
// Output GEMMs + tanh epilogue + scatter. A = sum of context halves.
// 32x64 tile, 128 threads, grid (4, 32, 2).  (unchanged from R11 best)
// =====================================================================
__global__ __launch_bounds__(128) void out_kernel(
    const float* __restrict__ W12, const float* __restrict__ b12,
    const float* __restrict__ W21, const float* __restrict__ b21,
    float* __restrict__ out)
{
    const int which = blockIdx.z;
    const float* A0   = which ? g_c12h[0] : g_c21h[0];
    const float* A1   = which ? g_c12h[1] : g_c21h[1];
    const float* Bm   = which ? (W12 + (size_t)D2N*BNN) : (W21 + (size_t)D1N*BNN);
    const float* bias = which ? b12 : b21;
    const float* Q    = which ? g_q2 : g_q1;
    float* O          = out + (which ? (size_t)L1N*BB*BNN : 0);
    const int i0 = blockIdx.y * 32;
    const int j0 = blockIdx.x * 64;
    const int tid = threadIdx.x;
    __shared__ __align__(16) float As[2][16][36];
    __shared__ __align__(16) float Bs[2][16][64];
    u64 acc[4][2] = {};
    const int ai = tid >> 2, ad = (tid & 3) << 2;
    const int bk = tid >> 4, bj = (tid & 15) << 2;
    const int ti = (tid >> 4) << 2, tj = (tid & 15) << 2;

    const size_t arow = (size_t)(i0+ai)*D1N + ad;
    float4 rA = f4add(*(const float4*)&A0[arow], *(const float4*)&A1[arow]);
    float4 rB0 = *(const float4*)&Bm[(size_t)bk*BNN + j0 + bj];
    float4 rB1 = *(const float4*)&Bm[(size_t)(bk+8)*BNN + j0 + bj];
    As[0][ad+0][ai]=rA.x; As[0][ad+1][ai]=rA.y; As[0][ad+2][ai]=rA.z; As[0][ad+3][ai]=rA.w;
    *(float4*)&Bs[0][bk  ][bj] = rB0;
    *(float4*)&Bs[0][bk+8][bj] = rB1;
    __syncthreads();

    const int T = D1N/16;
    #pragma unroll 1
    for (int t = 0; t < T; ++t) {
        const int cur = t & 1;
        if (t+1 < T) {
            rA  = f4add(*(const float4*)&A0[arow + (t+1)*16],
                        *(const float4*)&A1[arow + (t+1)*16]);
            rB0 = *(const float4*)&Bm[(size_t)((t+1)*16+bk  )*BNN + j0 + bj];
            rB1 = *(const float4*)&Bm[(size_t)((t+1)*16+bk+8)*BNN + j0 + bj];
        }
        #pragma unroll
        for (int k = 0; k < 16; ++k) FMA2_STEP(As[cur], Bs[cur], k);
        if (t+1 < T) {
            const int nxt = cur ^ 1;
            As[nxt][ad+0][ai]=rA.x; As[nxt][ad+1][ai]=rA.y;
            As[nxt][ad+2][ai]=rA.z; As[nxt][ad+3][ai]=rA.w;
            *(float4*)&Bs[nxt][bk  ][bj] = rB0;
            *(float4*)&Bs[nxt][bk+8][bj] = rB1;
            __syncthreads();
        }
    }
    const float4 bb = *(const float4*)&bias[j0+tj];
    #pragma unroll
    for (int r=0;r<4;r++){
        const int row = i0+ti+r;              // row = b*512 + seqpos
        const int b = row >> 9, sp = row & 511;
        const float4 q = *(const float4*)&Q[(size_t)row*BNN + j0 + tj];
        float2 lo = unpack2(acc[r][0]), hi = unpack2(acc[r][1]);
        float4 o;
        o.x = tanhf(lo.x+q.x+bb.x);
        o.y = tanhf(lo.y+q.y+bb.y);
        o.z = tanhf(hi.x+q.z+bb.z);
        o.w = tanhf(hi.y+q.w+bb.w);
        *(float4*)&O[((size_t)(sp*BB)+b)*BNN + j0 + tj] = o;
    }
}

// =====================================================================
extern "C" void kernel_launch(void* const* d_in, const int* in_sizes, int n_in,
                              void* d_out, int out_size)
{
    (void)in_sizes; (void)n_in; (void)out_size;
    const float* ctx1 = (const float*)d_in[0];
    const float* ctx2 = (const float*)d_in[1];
    const float* m1   = (const float*)d_in[2];
    const float* m2   = (const float*)d_in[3];
    const float* Wh   = (const float*)d_in[4];
    const float* bh   = (const float*)d_in[5];
    const float* wo   = (const float*)d_in[6];
    const float* W12  = (const float*)d_in[7];
    const float* b12  = (const float*)d_in[8];
    const float* W21  = (const float*)d_in[9];
    const float* b21  = (const float*)d_in[10];
    float* out = (float*)d_out;

    proj_p_kernel      <<<dim3(4, 8, 8),  256>>>(ctx1, ctx2, Wh, bh);
    affinity_q_kernel  <<<dim3(8, 8, 4),  256>>>(ctx1, ctx2, m1, m2, wo, W12, W21);
    softmax_dual_kernel<<<dim3(BB*L1N, 2), 128>>>();
    context_kernel     <<<dim3(4, 8, 8),  128>>>(ctx1, ctx2);
    out_kernel         <<<dim3(4, 32, 2), 128>>>(W12, b12, W21, b21, out);
}

// round 14
// speedup vs baseline: 1.1173x; 1.1173x over previous
#include <cuda_runtime.h>
#include <cuda_fp16.h>

#define L1N 512
#define L2N 512
#define BB  2
#define D1N 256
#define D2N 256
#define BNN 256
#define NEGC (-1.0e12f)

typedef unsigned long long u64;

// ---------------- device scratch (no allocations allowed) ----------------
__device__ float g_p1h[2][BB*L1N*BNN];   // K-split halves of p1 [b][l][k]
__device__ float g_p2h[2][BB*L2N*BNN];   // K-split halves of p2 (+bh in half 0)
__device__ float g_q1[BB*L1N*BNN];       // [b][l][k]
__device__ float g_q2[BB*L2N*BNN];       // [b][m][k]
__device__ float g_aff [BB*L1N*L2N];     // [b][l][m]
__device__ float g_afft[BB*L2N*L1N];     // [b][m][l]
__device__ float g_d12 [BB*L1N*L2N];     // softmax over m      [b][l][m]
__device__ float g_d21t[BB*L2N*L1N];     // softmax over l, T'd [b][m][l]
__device__ float g_c12h[2][BB*L2N*D1N];  // K-split halves [b][m][d]
__device__ float g_c21h[2][BB*L1N*D2N];  // K-split halves [b][l][d]

__device__ __forceinline__ u64 pack2(float v){
    u64 r; unsigned u = __float_as_uint(v);
    asm("mov.b64 %0, {%1, %2};" : "=l"(r) : "r"(u), "r"(u)); return r;
}
__device__ __forceinline__ u64 fma2(u64 a, u64 b, u64 c){
    u64 d; asm("fma.rn.f32x2 %0, %1, %2, %3;" : "=l"(d) : "l"(a), "l"(b), "l"(c));
    return d;
}
__device__ __forceinline__ float2 unpack2(u64 v){
    unsigned lo, hi;
    asm("mov.b64 {%0, %1}, %2;" : "=r"(lo), "=r"(hi) : "l"(v));
    return make_float2(__uint_as_float(lo), __uint_as_float(hi));
}
__device__ __forceinline__ float4 f4add(float4 a, float4 b){
    return make_float4(a.x+b.x, a.y+b.y, a.z+b.z, a.w+b.w);
}
// in-place packed half2 tanh (MUFU, no conversions)
__device__ __forceinline__ __half2 tanh_h2(__half2 x){
    unsigned u = *reinterpret_cast<unsigned*>(&x);
    asm("tanh.approx.f16x2 %0, %0;" : "+r"(u));
    return *reinterpret_cast<__half2*>(&u);
}

// 8×fma2 inner step on one k-slice of a 4x4 (as 4x2-pair) tile
#define FMA2_STEP(As_, Bs_, kk_)                                            \
    {                                                                        \
        const float4 a = *(const float4*)&As_[kk_][ti];                      \
        const ulonglong2 bb = *(const ulonglong2*)&Bs_[kk_][tj];             \
        const u64 a0 = pack2(a.x), a1 = pack2(a.y),                          \
                  a2 = pack2(a.z), a3 = pack2(a.w);                          \
        acc[0][0]=fma2(a0,bb.x,acc[0][0]); acc[0][1]=fma2(a0,bb.y,acc[0][1]);\
        acc[1][0]=fma2(a1,bb.x,acc[1][0]); acc[1][1]=fma2(a1,bb.y,acc[1][1]);\
        acc[2][0]=fma2(a2,bb.x,acc[2][0]); acc[2][1]=fma2(a2,bb.y,acc[2][1]);\
        acc[3][0]=fma2(a3,bb.x,acc[3][0]); acc[3][1]=fma2(a3,bb.y,acc[3][1]);\
    }

// =====================================================================
// p-projections, K-split 2x (R11 shape):
// grid (4, 8, 8), 256 threads. Reads only harness inputs (no PDL sync).
// =====================================================================
__global__ __launch_bounds__(256) void proj_p_kernel(
    const float* __restrict__ ctx1, const float* __restrict__ ctx2,
    const float* __restrict__ Wh,  const float* __restrict__ bh)
{
    const int mode = blockIdx.z >> 2;
    const int b    = (blockIdx.z >> 1) & 1;
    const int ks   = blockIdx.z & 1;
    const float* X = mode ? ctx2 : ctx1;
    const float* W = mode ? (Wh + (size_t)D1N*BNN) : Wh;
    float* P       = mode ? g_p2h[ks] : g_p1h[ks];
    const bool addb = (mode == 1) && (ks == 0);

    const int i0 = blockIdx.y * 64;
    const int j0 = blockIdx.x * 64;
    const int k00 = ks * 128;
    const int tid = threadIdx.x;
    __shared__ __align__(16) float As[2][16][68];
    __shared__ __align__(16) float Bs[2][16][64];
    u64 acc[4][2] = {};
    const int ai = tid >> 2, ad = (tid & 3) << 2;
    const int bk = tid >> 4, bj = (tid & 15) << 2;
    const int ti = (tid >> 4) << 2, tj = (tid & 15) << 2;

    const size_t arow = ((size_t)(i0+ai)*BB + b)*D1N + k00 + ad;
    float4 rA = *(const float4*)&X[arow];
    float4 rB = *(const float4*)&W[(size_t)(k00+bk)*BNN + j0 + bj];
    As[0][ad+0][ai]=rA.x; As[0][ad+1][ai]=rA.y; As[0][ad+2][ai]=rA.z; As[0][ad+3][ai]=rA.w;
    *(float4*)&Bs[0][bk][bj] = rB;
    __syncthreads();

    const int T = 128/16;
    #pragma unroll 1
    for (int t = 0; t < T; ++t) {
        const int cur = t & 1;
        if (t+1 < T) {
            rA = *(const float4*)&X[arow + (t+1)*16];
            rB = *(const float4*)&W[(size_t)(k00+(t+1)*16+bk)*BNN + j0 + bj];
        }
        #pragma unroll
        for (int k = 0; k < 16; ++k) FMA2_STEP(As[cur], Bs[cur], k);
        if (t+1 < T) {
            const int nxt = cur ^ 1;
            As[nxt][ad+0][ai]=rA.x; As[nxt][ad+1][ai]=rA.y;
            As[nxt][ad+2][ai]=rA.z; As[nxt][ad+3][ai]=rA.w;
            *(float4*)&Bs[nxt][bk][bj] = rB;
            __syncthreads();
        }
    }
    float4 bb = addb ? *(const float4*)&bh[j0+tj] : make_float4(0.f,0.f,0.f,0.f);
    #pragma unroll
    for (int r=0;r<4;r++){
        float2 lo = unpack2(acc[r][0]), hi = unpack2(acc[r][1]);
        float4 o = make_float4(lo.x+bb.x, lo.y+bb.y, hi.x+bb.z, hi.y+bb.w);
        *(float4*)&P[((size_t)(b*L1N)+(i0+ti+r))*BNN + j0 + tj] = o;
    }
}

// =====================================================================
// Heterogeneous: affinity (z=0,1) + q-projections (z=2: q1, z=3: q2).
// grid (8, 8, 4), 256 threads. PDL: q path needs NO sync (inputs only);
// affinity path syncs before reading g_p1h/g_p2h.
// =====================================================================
__global__ __launch_bounds__(256) void affinity_q_kernel(
    const float* __restrict__ ctx1, const float* __restrict__ ctx2,
    const float* __restrict__ m1, const float* __restrict__ m2,
    const float* __restrict__ wo,
    const float* __restrict__ W12, const float* __restrict__ W21)
{
    const int tid = threadIdx.x;
    if (blockIdx.z >= 2) {
        // ---------------- q-projection path (no dependency on proj) -------
        const int qmode = blockIdx.z - 2;          // 0: q1, 1: q2
        const float* X = qmode ? ctx2 : ctx1;
        const float* W = qmode ? W12  : W21;
        float* P       = qmode ? g_q2 : g_q1;
        const int b  = blockIdx.x >> 2;
        const int j0 = (blockIdx.x & 3) * 64;
        const int i0 = blockIdx.y * 64;
        __shared__ __align__(16) float As[2][16][68];
        __shared__ __align__(16) float Bs[2][16][64];
        u64 acc[4][2] = {};
        const int ai = tid >> 2, ad = (tid & 3) << 2;
        const int bk = tid >> 4, bj = (tid & 15) << 2;
        const int ti = (tid >> 4) << 2, tj = (tid & 15) << 2;

        const size_t arow = ((size_t)(i0+ai)*BB + b)*D1N + ad;
        float4 rA = *(const float4*)&X[arow];
        float4 rB = *(const float4*)&W[(size_t)bk*BNN + j0 + bj];
        As[0][ad+0][ai]=rA.x; As[0][ad+1][ai]=rA.y; As[0][ad+2][ai]=rA.z; As[0][ad+3][ai]=rA.w;
        *(float4*)&Bs[0][bk][bj] = rB;
        __syncthreads();

        const int T = D1N/16;
        #pragma unroll 1
        for (int t = 0; t < T; ++t) {
            const int cur = t & 1;
            if (t+1 < T) {
                rA = *(const float4*)&X[arow + (t+1)*16];
                rB = *(const float4*)&W[(size_t)((t+1)*16+bk)*BNN + j0 + bj];
            }
            #pragma unroll
            for (int k = 0; k < 16; ++k) FMA2_STEP(As[cur], Bs[cur], k);
            if (t+1 < T) {
                const int nxt = cur ^ 1;
                As[nxt][ad+0][ai]=rA.x; As[nxt][ad+1][ai]=rA.y;
                As[nxt][ad+2][ai]=rA.z; As[nxt][ad+3][ai]=rA.w;
                *(float4*)&Bs[nxt][bk][bj] = rB;
                __syncthreads();
            }
        }
        #pragma unroll
        for (int r=0;r<4;r++){
            float2 lo = unpack2(acc[r][0]), hi = unpack2(acc[r][1]);
            *(float4*)&P[((size_t)(b*L1N)+(i0+ti+r))*BNN + j0 + tj]
                = make_float4(lo.x,lo.y,hi.x,hi.y);
        }
        return;
    }
    // ---------------- affinity path (all-fp16 inner loop) ----------------
    const int b  = blockIdx.z;
    const int l0 = blockIdx.y * 64;
    const int m0 = blockIdx.x * 64;
    __shared__ __align__(16) __half P1s[2][16][72];   // [buf][k][l-col], half
    __shared__ __align__(16) __half P2s[2][16][72];   // [buf][k][m-col], half
    __shared__ __half2 wos2[BNN];
    wos2[tid] = __float2half2_rn(wo[tid]);            // input read: OK pre-sync
    float acc[4][4] = {};
    const int ai = tid >> 2, ad = (tid & 3) << 2;
    const int ti = (tid >> 4) << 2, tm = (tid & 15) << 2;

    const size_t prow1 = ((size_t)(b*L1N)+(l0+ai))*BNN + ad;
    const size_t prow2 = ((size_t)(b*L2N)+(m0+ai))*BNN + ad;

    cudaGridDependencySynchronize();   // wait for proj_p outputs

    float4 rA = f4add(*(const float4*)&g_p1h[0][prow1],
                      *(const float4*)&g_p1h[1][prow1]);
    float4 rB = f4add(*(const float4*)&g_p2h[0][prow2],
                      *(const float4*)&g_p2h[1][prow2]);
    P1s[0][ad+0][ai]=__float2half(rA.x); P1s[0][ad+1][ai]=__float2half(rA.y);
    P1s[0][ad+2][ai]=__float2half(rA.z); P1s[0][ad+3][ai]=__float2half(rA.w);
    P2s[0][ad+0][ai]=__float2half(rB.x); P2s[0][ad+1][ai]=__float2half(rB.y);
    P2s[0][ad+2][ai]=__float2half(rB.z); P2s[0][ad+3][ai]=__float2half(rB.w);
    __syncthreads();

    const int T = BNN/16;
    #pragma unroll 1
    for (int t = 0; t < T; ++t) {
        const int cur = t & 1;
        if (t+1 < T) {
            rA = f4add(*(const float4*)&g_p1h[0][prow1 + (t+1)*16],
                       *(const float4*)&g_p1h[1][prow1 + (t+1)*16]);
            rB = f4add(*(const float4*)&g_p2h[0][prow2 + (t+1)*16],
                       *(const float4*)&g_p2h[1][prow2 + (t+1)*16]);
        }
        __half2 hacc[4][2];
        #pragma unroll
        for (int r=0;r<4;r++){ hacc[r][0]=__half2half2(__ushort_as_half(0));
                               hacc[r][1]=__half2half2(__ushort_as_half(0)); }
        #pragma unroll
        for (int kk = 0; kk < 16; ++kk) {
            const __half2 w2 = wos2[t*16+kk];
            __half a4[4];
            *reinterpret_cast<uint2*>(a4)
                = *reinterpret_cast<const uint2*>(&P1s[cur][kk][ti]);
            __half2 cv[2];
            *reinterpret_cast<uint2*>(cv)
                = *reinterpret_cast<const uint2*>(&P2s[cur][kk][tm]);
            #pragma unroll
            for (int r=0;r<4;r++){
                const __half2 ar2 = __half2half2(a4[r]);
                const __half2 t0 = tanh_h2(__hadd2(ar2, cv[0]));
                const __half2 t1 = tanh_h2(__hadd2(ar2, cv[1]));
                hacc[r][0] = __hfma2(w2, t0, hacc[r][0]);
                hacc[r][1] = __hfma2(w2, t1, hacc[r][1]);
            }
        }
        #pragma unroll
        for (int r=0;r<4;r++){
            const float2 f0 = __half22float2(hacc[r][0]);
            const float2 f1 = __half22float2(hacc[r][1]);
            acc[r][0]+=f0.x; acc[r][1]+=f0.y; acc[r][2]+=f1.x; acc[r][3]+=f1.y;
        }
        if (t+1 < T) {
            const int nxt = cur ^ 1;
            P1s[nxt][ad+0][ai]=__float2half(rA.x); P1s[nxt][ad+1][ai]=__float2half(rA.y);
            P1s[nxt][ad+2][ai]=__float2half(rA.z); P1s[nxt][ad+3][ai]=__float2half(rA.w);
            P2s[nxt][ad+0][ai]=__float2half(rB.x); P2s[nxt][ad+1][ai]=__float2half(rB.y);
            P2s[nxt][ad+2][ai]=__float2half(rB.z); P2s[nxt][ad+3][ai]=__float2half(rB.w);
            __syncthreads();
        }
    }
    float mrow[4], mcol[4];
    #pragma unroll
    for (int r=0;r<4;r++) mrow[r] = (1.0f - m1[(l0+ti+r)*BB + b]) * NEGC;
    #pragma unroll
    for (int c=0;c<4;c++) mcol[c] = (1.0f - m2[(m0+tm+c)*BB + b]) * NEGC;
    #pragma unroll
    for (int r=0;r<4;r++)
        #pragma unroll
        for (int c=0;c<4;c++)
            acc[r][c] += mrow[r] + mcol[c];
    #pragma unroll
    for (int r=0;r<4;r++)
        *(float4*)&g_aff[((size_t)(b*L1N)+(l0+ti+r))*L2N + m0 + tm]
            = make_float4(acc[r][0],acc[r][1],acc[r][2],acc[r][3]);
    #pragma unroll
    for (int c=0;c<4;c++)
        *(float4*)&g_afft[((size_t)(b*L2N)+(m0+tm+c))*L1N + l0 + ti]
            = make_float4(acc[0][c],acc[1][c],acc[2][c],acc[3][c]);
}

// =====================================================================
// Dual row softmax: grid (B*512, 2). PDL sync before reading g_aff/g_afft.
// =====================================================================
__global__ __launch_bounds__(128) void softmax_dual_kernel()
{
    const int row = blockIdx.x;
    const float* src = blockIdx.y ? g_afft : g_aff;
    float*       dst = blockIdx.y ? g_d21t : g_d12;
    cudaGridDependencySynchronize();
    const float4 v = ((const float4*)&src[(size_t)row*512])[threadIdx.x];
    float mx = fmaxf(fmaxf(v.x,v.y), fmaxf(v.z,v.w));
    #pragma unroll
    for (int o=16;o;o>>=1) mx = fmaxf(mx, __shfl_xor_sync(0xffffffffu, mx, o));
    __shared__ float redm[4], reds[4];
    const int wid = threadIdx.x >> 5, lane = threadIdx.x & 31;
    if (!lane) redm[wid] = mx;
    __syncthreads();
    mx = fmaxf(fmaxf(redm[0],redm[1]), fmaxf(redm[2],redm[3]));
    float e0=__expf(v.x-mx), e1=__expf(v.y-mx), e2=__expf(v.z-mx), e3=__expf(v.w-mx);
    float s = (e0+e1)+(e2+e3);
    #pragma unroll
    for (int o=16;o;o>>=1) s += __shfl_xor_sync(0xffffffffu, s, o);
    if (!lane) reds[wid] = s;
    __syncthreads();
    s = (reds[0]+reds[1])+(reds[2]+reds[3]);
    const float inv = 1.0f / s;
    ((float4*)&dst[(size_t)row*512])[threadIdx.x]
        = make_float4(e0*inv, e1*inv, e2*inv, e3*inv);
}

// =====================================================================
// Context GEMMs, K-split 2x (R11 shape): grid (4, 8, 8), 256 threads.
// PDL sync before reading g_d12/g_d21t.
// =====================================================================
__global__ __launch_bounds__(256) void context_kernel(
    const float* __restrict__ ctx1, const float* __restrict__ ctx2)
{
    const int which = blockIdx.z >> 2;
    const int b     = (blockIdx.z >> 1) & 1;
    const int ks    = blockIdx.z & 1;
    const float* Asrc = which ? g_d21t : g_d12;
    const float* Bsrc = which ? ctx2   : ctx1;
    float*       Cdst = which ? g_c21h[ks] : g_c12h[ks];
    const int i0 = blockIdx.y * 64;
    const int j0 = blockIdx.x * 64;
    const int k00 = ks * 256;
    const int tid = threadIdx.x;
    __shared__ __align__(16) float As[2][16][68];
    __shared__ __align__(16) float Bs[2][16][64];
    u64 acc[4][2] = {};
    const int ak = tid >> 4, am = (tid & 15) << 2;
    const int bk = tid >> 4, bj = (tid & 15) << 2;
    const int ti = (tid >> 4) << 2, tj = (tid & 15) << 2;

    cudaGridDependencySynchronize();

    float4 rA = *(const float4*)&Asrc[((size_t)(b*L1N)+(k00+ak))*L2N + i0 + am];
    float4 rB = *(const float4*)&Bsrc[((size_t)(k00+bk)*BB + b)*D1N + j0 + bj];
    *(float4*)&As[0][ak][am] = rA;
    *(float4*)&Bs[0][bk][bj] = rB;
    __syncthreads();

    const int T = 256/16;
    #pragma unroll 1
    for (int t = 0; t < T; ++t) {
        const int cur = t & 1;
        if (t+1 < T) {
            const int kn = k00 + (t+1)*16;
            rA = *(const float4*)&Asrc[((size_t)(b*L1N)+(kn+ak))*L2N + i0 + am];
            rB = *(const float4*)&Bsrc[((size_t)(kn+bk)*BB + b)*D1N + j0 + bj];
        }
        #pragma unroll
        for (int k = 0; k < 16; ++k) FMA2_STEP(As[cur], Bs[cur], k);
        if (t+1 < T) {
            const int nxt = cur ^ 1;
            *(float4*)&As[nxt][ak][am] = rA;
            *(float4*)&Bs[nxt][bk][bj] = rB;
            __syncthreads();
        }
    }
    #pragma unroll
    for (int r=0;r<4;r++){
        float2 lo = unpack2(acc[r][0]), hi = unpack2(acc[r][1]);
        *(float4*)&Cdst[((size_t)(b*L1N)+(i0+ti+r))*D1N + j0 + tj]
            = make_float4(lo.x,lo.y,hi.x,hi.y);
    }
}

// =====================================================================
// Output GEMMs + tanh epilogue + scatter (R11 shape):
// 32x64 tile, 128 threads, grid (4, 32, 2). PDL sync before c-halves read.
// =====================================================================
__global__ __launch_bounds__(128) void out_kernel(
    const float* __restrict__ W12, const float* __restrict__ b12,
    const float* __restrict__ W21, const float* __restrict__ b21,
    float* __restrict__ out)
{
    const int which = blockIdx.z;
    const float* A0   = which ? g_c12h[0] : g_c21h[0];
    const float* A1   = which ? g_c12h[1] : g_c21h[1];
    const float* Bm   = which ? (W12 + (size_t)D2N*BNN) : (W21 + (size_t)D1N*BNN);
    const float* bias = which ? b12 : b21;
    const float* Q    = which ? g_q2 : g_q1;
    float* O          = out + (which ? (size_t)L1N*BB*BNN : 0);
    const int i0 = blockIdx.y * 32;
    const int j0 = blockIdx.x * 64;
    const int tid = threadIdx.x;
    __shared__ __align__(16) float As[2][16][36];
    __shared__ __align__(16) float Bs[2][16][64];
    u64 acc[4][2] = {};
    const int ai = tid >> 2, ad = (tid & 3) << 2;
    const int bk = tid >> 4, bj = (tid & 15) << 2;
    const int ti = (tid >> 4) << 2, tj = (tid & 15) << 2;

    const size_t arow = (size_t)(i0+ai)*D1N + ad;
    // B (weights) are harness inputs — prefetch before the dependency sync
    float4 rB0 = *(const float4*)&Bm[(size_t)bk*BNN + j0 + bj];
    float4 rB1 = *(const float4*)&Bm[(size_t)(bk+8)*BNN + j0 + bj];

    cudaGridDependencySynchronize();

    float4 rA = f4add(*(const float4*)&A0[arow], *(const float4*)&A1[arow]);
    As[0][ad+0][ai]=rA.x; As[0][ad+1][ai]=rA.y; As[0][ad+2][ai]=rA.z; As[0][ad+3][ai]=rA.w;
    *(float4*)&Bs[0][bk  ][bj] = rB0;
    *(float4*)&Bs[0][bk+8][bj] = rB1;
    __syncthreads();

    const int T = D1N/16;
    #pragma unroll 1
    for (int t = 0; t < T; ++t) {
        const int cur = t & 1;
        if (t+1 < T) {
            rA  = f4add(*(const float4*)&A0[arow + (t+1)*16],
                        *(const float4*)&A1[arow + (t+1)*16]);
            rB0 = *(const float4*)&Bm[(size_t)((t+1)*16+bk  )*BNN + j0 + bj];
            rB1 = *(const float4*)&Bm[(size_t)((t+1)*16+bk+8)*BNN + j0 + bj];
        }
        #pragma unroll
        for (int k = 0; k < 16; ++k) FMA2_STEP(As[cur], Bs[cur], k);
        if (t+1 < T) {
            const int nxt = cur ^ 1;
            As[nxt][ad+0][ai]=rA.x; As[nxt][ad+1][ai]=rA.y;
            As[nxt][ad+2][ai]=rA.z; As[nxt][ad+3][ai]=rA.w;
            *(float4*)&Bs[nxt][bk  ][bj] = rB0;
            *(float4*)&Bs[nxt][bk+8][bj] = rB1;
            __syncthreads();
        }
    }
    const float4 bb = *(const float4*)&bias[j0+tj];
    #pragma unroll
    for (int r=0;r<4;r++){
        const int row = i0+ti+r;              // row = b*512 + seqpos
        const int b = row >> 9, sp = row & 511;
        const float4 q = *(const float4*)&Q[(size_t)row*BNN + j0 + tj];
        float2 lo = unpack2(acc[r][0]), hi = unpack2(acc[r][1]);
        float4 o;
        o.x = tanhf(lo.x+q.x+bb.x);
        o.y = tanhf(lo.y+q.y+bb.y);
        o.z = tanhf(hi.x+q.z+bb.z);
        o.w = tanhf(hi.y+q.w+bb.w);
        *(float4*)&O[((size_t)(sp*BB)+b)*BNN + j0 + tj] = o;
    }
}

// =====================================================================
// Host: launch chain with programmatic dependent launch (PDL) so each
// stage's launch/prologue overlaps the predecessor's tail.
// =====================================================================
static inline void launch_ex(const void* func, dim3 grid, dim3 block,
                             void** args, bool pdl)
{
    cudaLaunchConfig_t cfg = {};
    cfg.gridDim = grid;
    cfg.blockDim = block;
    cfg.dynamicSmemBytes = 0;
    cfg.stream = 0;
    cudaLaunchAttribute attr[1];
    if (pdl) {
        attr[0].id = cudaLaunchAttributeProgrammaticStreamSerialization;
        attr[0].val.programmaticStreamSerializationAllowed = 1;
        cfg.attrs = attr;
        cfg.numAttrs = 1;
    }
    cudaLaunchKernelExC(&cfg, func, args);
}

extern "C" void kernel_launch(void* const* d_in, const int* in_sizes, int n_in,
                              void* d_out, int out_size)
{
    (void)in_sizes; (void)n_in; (void)out_size;
    const float* ctx1 = (const float*)d_in[0];
    const float* ctx2 = (const float*)d_in[1];
    const float* m1   = (const float*)d_in[2];
    const float* m2   = (const float*)d_in[3];
    const float* Wh   = (const float*)d_in[4];
    const float* bh   = (const float*)d_in[5];
    const float* wo   = (const float*)d_in[6];
    const float* W12  = (const float*)d_in[7];
    const float* b12  = (const float*)d_in[8];
    const float* W21  = (const float*)d_in[9];
    const float* b21  = (const float*)d_in[10];
    float* out = (float*)d_out;

    {
        void* args[] = {(void*)&ctx1, (void*)&ctx2, (void*)&Wh, (void*)&bh};
        launch_ex((const void*)proj_p_kernel, dim3(4,8,8), dim3(256), args, false);
    }
    {
        void* args[] = {(void*)&ctx1, (void*)&ctx2, (void*)&m1, (void*)&m2,
                        (void*)&wo, (void*)&W12, (void*)&W21};
        launch_ex((const void*)affinity_q_kernel, dim3(8,8,4), dim3(256), args, true);
    }
    {
        void* args[] = {};
        launch_ex((const void*)softmax_dual_kernel, dim3(BB*L1N,2), dim3(128),
                  args, true);
    }
    {
        void* args[] = {(void*)&ctx1, (void*)&ctx2};
        launch_ex((const void*)context_kernel, dim3(4,8,8), dim3(256), args, true);
    }
    {
        void* args[] = {(void*)&W12, (void*)&b12, (void*)&W21, (void*)&b21,
                        (void*)&out};
        launch_ex((const void*)out_kernel, dim3(4,32,2), dim3(128), args, true);
    }
}